// round 1
// baseline (speedup 1.0000x reference)
#include <cuda_runtime.h>
#include <cstdint>

// Problem constants
#define B_    8192
#define C_    4096
#define G_    8
#define HID_  1024
#define CTRL_ 64
#define NH_   (G_*HID_)   // 8192 stacked hidden width

// Scratch: H = choose-weighted relu(x@w1+b1), stacked [B, G*HID]
__device__ float g_H[(size_t)B_ * NH_];
// choose[b][g] softmax gate weights
__device__ float g_choose[B_ * G_];

// ---------------------------------------------------------------------------
// helpers
// ---------------------------------------------------------------------------
__device__ __forceinline__ unsigned f2tf32(float x) {
    unsigned u;
    asm("cvt.rna.tf32.f32 %0, %1;" : "=r"(u) : "f"(x));
    return u;
}

__device__ __forceinline__ void mma_m16n8k8(float c[4], const unsigned a[4], const unsigned b[2]) {
    asm volatile(
        "mma.sync.aligned.m16n8k8.row.col.f32.tf32.tf32.f32 "
        "{%0,%1,%2,%3}, {%4,%5,%6,%7}, {%8,%9}, {%0,%1,%2,%3};"
        : "+f"(c[0]), "+f"(c[1]), "+f"(c[2]), "+f"(c[3])
        : "r"(a[0]), "r"(a[1]), "r"(a[2]), "r"(a[3]),
          "r"(b[0]), "r"(b[1]));
}

// Store one 128x16 A tile (transposed: As[k][m]) and 16x128 B tile (Bs[k][n]),
// tf32-rounding each element.
__device__ __forceinline__ void stash_tiles(
    float (*As)[136], float (*Bs)[136],
    float4 ra0, float4 ra1, float4 rb0, float4 rb1,
    int aRow0, int aK0, int bRow0, int bCol0)
{
    As[aK0 + 0][aRow0]      = __uint_as_float(f2tf32(ra0.x));
    As[aK0 + 1][aRow0]      = __uint_as_float(f2tf32(ra0.y));
    As[aK0 + 2][aRow0]      = __uint_as_float(f2tf32(ra0.z));
    As[aK0 + 3][aRow0]      = __uint_as_float(f2tf32(ra0.w));
    As[aK0 + 0][aRow0 + 64] = __uint_as_float(f2tf32(ra1.x));
    As[aK0 + 1][aRow0 + 64] = __uint_as_float(f2tf32(ra1.y));
    As[aK0 + 2][aRow0 + 64] = __uint_as_float(f2tf32(ra1.z));
    As[aK0 + 3][aRow0 + 64] = __uint_as_float(f2tf32(ra1.w));

    float4 t0;
    t0.x = __uint_as_float(f2tf32(rb0.x));
    t0.y = __uint_as_float(f2tf32(rb0.y));
    t0.z = __uint_as_float(f2tf32(rb0.z));
    t0.w = __uint_as_float(f2tf32(rb0.w));
    *reinterpret_cast<float4*>(&Bs[bRow0][bCol0]) = t0;

    float4 t1;
    t1.x = __uint_as_float(f2tf32(rb1.x));
    t1.y = __uint_as_float(f2tf32(rb1.y));
    t1.z = __uint_as_float(f2tf32(rb1.z));
    t1.w = __uint_as_float(f2tf32(rb1.w));
    *reinterpret_cast<float4*>(&Bs[bRow0 + 8][bCol0]) = t1;
}

// Main GEMM loop: C_tile(128x128) += A[m0:m0+128, :K] * B[:, bcol0:bcol0+128]
// A row-major (lda), B row-major (ldb). acc is the per-thread mma accumulator.
__device__ __forceinline__ void run_gemm(
    const float* __restrict__ Ag, const float* __restrict__ Bg,
    int lda, int ldb, int K, int m0, int bcol0,
    float acc[2][8][4])
{
    __shared__ alignas(16) float As[2][16][136];
    __shared__ alignas(16) float Bs[2][16][136];

    const int tid = threadIdx.x;
#pragma unroll
    for (int i = 0; i < 2; i++)
#pragma unroll
        for (int j = 0; j < 8; j++)
#pragma unroll
            for (int k = 0; k < 4; k++) acc[i][j][k] = 0.f;

    const int aRow0 = tid >> 2;          // 0..63
    const int aK0   = (tid & 3) * 4;     // 0,4,8,12
    const int bRow0 = tid >> 5;          // 0..7
    const int bCol0 = (tid & 31) * 4;    // 0..124

    const float* aP0 = Ag + (size_t)(m0 + aRow0) * lda + aK0;
    const float* aP1 = aP0 + (size_t)64 * lda;
    const float* bP0 = Bg + (size_t)bRow0 * ldb + bcol0 + bCol0;
    const float* bP1 = bP0 + (size_t)8 * ldb;

    float4 ra0 = *reinterpret_cast<const float4*>(aP0);
    float4 ra1 = *reinterpret_cast<const float4*>(aP1);
    float4 rb0 = *reinterpret_cast<const float4*>(bP0);
    float4 rb1 = *reinterpret_cast<const float4*>(bP1);
    stash_tiles(As[0], Bs[0], ra0, ra1, rb0, rb1, aRow0, aK0, bRow0, bCol0);
    __syncthreads();

    const int lane = tid & 31;
    const int warp = tid >> 5;
    const int wm = (warp & 3) * 32;      // warp M offset
    const int wn = (warp >> 2) * 64;     // warp N offset
    const int g8 = lane >> 2;
    const int tg = lane & 3;

    const int nk = K >> 4;
    for (int t = 0; t < nk; ++t) {
        const int buf = t & 1;
        if (t + 1 < nk) {
            ra0 = *reinterpret_cast<const float4*>(aP0 + (size_t)(t + 1) * 16);
            ra1 = *reinterpret_cast<const float4*>(aP1 + (size_t)(t + 1) * 16);
            rb0 = *reinterpret_cast<const float4*>(bP0 + (size_t)(t + 1) * 16 * ldb);
            rb1 = *reinterpret_cast<const float4*>(bP1 + (size_t)(t + 1) * 16 * ldb);
        }
#pragma unroll
        for (int k8 = 0; k8 < 16; k8 += 8) {
            unsigned a[2][4], b[8][2];
#pragma unroll
            for (int im = 0; im < 2; im++) {
                const int mb = wm + im * 16 + g8;
                a[im][0] = __float_as_uint(As[buf][k8 + tg][mb]);
                a[im][1] = __float_as_uint(As[buf][k8 + tg][mb + 8]);
                a[im][2] = __float_as_uint(As[buf][k8 + 4 + tg][mb]);
                a[im][3] = __float_as_uint(As[buf][k8 + 4 + tg][mb + 8]);
            }
#pragma unroll
            for (int in = 0; in < 8; in++) {
                const int nb = wn + in * 8 + g8;
                b[in][0] = __float_as_uint(Bs[buf][k8 + tg][nb]);
                b[in][1] = __float_as_uint(Bs[buf][k8 + 4 + tg][nb]);
            }
#pragma unroll
            for (int im = 0; im < 2; im++)
#pragma unroll
                for (int in = 0; in < 8; in++)
                    mma_m16n8k8(acc[im][in], a[im], b[in]);
        }
        if (t + 1 < nk)
            stash_tiles(As[buf ^ 1], Bs[buf ^ 1], ra0, ra1, rb0, rb1,
                        aRow0, aK0, bRow0, bCol0);
        __syncthreads();
    }
}

// ---------------------------------------------------------------------------
// Gate control: choose = softmax(relu(y@wc1+bc1)@wc2+bc2)
// ---------------------------------------------------------------------------
__global__ __launch_bounds__(256)
void gate_kernel(const float* __restrict__ y,
                 const float* __restrict__ wc1, const float* __restrict__ bc1,
                 const float* __restrict__ wc2, const float* __restrict__ bc2)
{
    __shared__ float swc1[CTRL_ * G_];
    __shared__ float swc2[G_ * G_];
    __shared__ float sbc1[G_];
    __shared__ float sbc2[G_];
    const int tid = threadIdx.x;
    for (int i = tid; i < CTRL_ * G_; i += 256) swc1[i] = wc1[i];
    if (tid < G_ * G_) swc2[tid] = wc2[tid];
    if (tid < G_) { sbc1[tid] = bc1[tid]; sbc2[tid] = bc2[tid]; }
    __syncthreads();

    const int b = blockIdx.x * 256 + tid;
    const float* yr = y + (size_t)b * CTRL_;

    float hid[G_];
#pragma unroll
    for (int j = 0; j < G_; j++) hid[j] = sbc1[j];
    for (int c = 0; c < CTRL_; c++) {
        const float yv = yr[c];
#pragma unroll
        for (int j = 0; j < G_; j++) hid[j] += yv * swc1[c * G_ + j];
    }
#pragma unroll
    for (int j = 0; j < G_; j++) hid[j] = fmaxf(hid[j], 0.f);

    float o[G_];
#pragma unroll
    for (int g = 0; g < G_; g++) o[g] = sbc2[g];
#pragma unroll
    for (int j = 0; j < G_; j++)
#pragma unroll
        for (int g = 0; g < G_; g++) o[g] += hid[j] * swc2[j * G_ + g];

    float mx = o[0];
#pragma unroll
    for (int g = 1; g < G_; g++) mx = fmaxf(mx, o[g]);
    float s = 0.f;
#pragma unroll
    for (int g = 0; g < G_; g++) { o[g] = __expf(o[g] - mx); s += o[g]; }
    const float inv = 1.f / s;
#pragma unroll
    for (int g = 0; g < G_; g++) g_choose[b * G_ + g] = o[g] * inv;
}

// ---------------------------------------------------------------------------
// GEMM1: g_H[b, g*1024+h] = choose[b,g] * relu(x @ w1_g + b1_g)
// ---------------------------------------------------------------------------
__global__ __launch_bounds__(256)
void gemm1_kernel(const float* __restrict__ x,
                  const float* __restrict__ w1,
                  const float* __restrict__ b1)
{
    const int n0 = blockIdx.x * 128;   // column in stacked [0, 8192)
    const int m0 = blockIdx.y * 128;
    const int g  = n0 / HID_;
    const int h0 = n0 % HID_;

    __shared__ float sCh[128];   // choose[m0+i][g]
    __shared__ float sBi[128];   // b1[g][h0+i]
    const int tid = threadIdx.x;
    if (tid < 128) {
        sCh[tid] = g_choose[(m0 + tid) * G_ + g];
        sBi[tid] = b1[g * HID_ + h0 + tid];
    }
    // (first __syncthreads inside run_gemm orders these writes)

    float acc[2][8][4];
    const float* Bg = w1 + (size_t)g * C_ * HID_;   // [C_, HID_] row-major
    run_gemm(x, Bg, C_, HID_, C_, m0, h0, acc);

    const int lane = tid & 31;
    const int warp = tid >> 5;
    const int wm = (warp & 3) * 32;
    const int wn = (warp >> 2) * 64;
    const int g8 = lane >> 2;
    const int tg = lane & 3;

#pragma unroll
    for (int im = 0; im < 2; im++) {
        const int r0 = wm + im * 16 + g8;
        const float w0 = sCh[r0];
        const float w1v = sCh[r0 + 8];
#pragma unroll
        for (int in = 0; in < 8; in++) {
            const int c0 = wn + in * 8 + tg * 2;
            const float bi0 = sBi[c0];
            const float bi1 = sBi[c0 + 1];
            float2 v0, v1;
            v0.x = fmaxf(acc[im][in][0] + bi0, 0.f) * w0;
            v0.y = fmaxf(acc[im][in][1] + bi1, 0.f) * w0;
            v1.x = fmaxf(acc[im][in][2] + bi0, 0.f) * w1v;
            v1.y = fmaxf(acc[im][in][3] + bi1, 0.f) * w1v;
            *reinterpret_cast<float2*>(&g_H[(size_t)(m0 + r0) * NH_ + n0 + c0]) = v0;
            *reinterpret_cast<float2*>(&g_H[(size_t)(m0 + r0 + 8) * NH_ + n0 + c0]) = v1;
        }
    }
}

// ---------------------------------------------------------------------------
// GEMM2: out[b,c] = g_H[b,:] @ W2stacked[:,c] + sum_g choose[b,g]*b2[g,c]
// ---------------------------------------------------------------------------
__global__ __launch_bounds__(256)
void gemm2_kernel(const float* __restrict__ w2,
                  const float* __restrict__ b2,
                  float* __restrict__ out)
{
    const int n0 = blockIdx.x * 128;
    const int m0 = blockIdx.y * 128;

    __shared__ float sCh[128 * G_];  // choose rows m0..m0+127 (contiguous)
    __shared__ float sB2[G_ * 128];  // b2[g][n0..n0+127]
    const int tid = threadIdx.x;
    for (int i = tid; i < 128 * G_; i += 256) sCh[i] = g_choose[m0 * G_ + i];
    for (int i = tid; i < G_ * 128; i += 256) {
        const int gg = i >> 7, cc = i & 127;
        sB2[i] = b2[gg * C_ + n0 + cc];
    }

    float acc[2][8][4];
    // w2 as [G*HID, C] row-major is exactly the stacked B matrix.
    run_gemm(g_H, w2, NH_, C_, NH_, m0, n0, acc);

    const int lane = tid & 31;
    const int warp = tid >> 5;
    const int wm = (warp & 3) * 32;
    const int wn = (warp >> 2) * 64;
    const int g8 = lane >> 2;
    const int tg = lane & 3;

#pragma unroll
    for (int im = 0; im < 2; im++) {
        const int r0 = wm + im * 16 + g8;
#pragma unroll
        for (int in = 0; in < 8; in++) {
            const int c0 = wn + in * 8 + tg * 2;
            float v00 = acc[im][in][0], v01 = acc[im][in][1];
            float v10 = acc[im][in][2], v11 = acc[im][in][3];
#pragma unroll
            for (int g = 0; g < G_; g++) {
                const float ch0 = sCh[r0 * G_ + g];
                const float ch1 = sCh[(r0 + 8) * G_ + g];
                const float bb0 = sB2[g * 128 + c0];
                const float bb1 = sB2[g * 128 + c0 + 1];
                v00 += ch0 * bb0; v01 += ch0 * bb1;
                v10 += ch1 * bb0; v11 += ch1 * bb1;
            }
            float2 o0 = {v00, v01};
            float2 o1 = {v10, v11};
            *reinterpret_cast<float2*>(&out[(size_t)(m0 + r0) * C_ + n0 + c0]) = o0;
            *reinterpret_cast<float2*>(&out[(size_t)(m0 + r0 + 8) * C_ + n0 + c0]) = o1;
        }
    }
}

// ---------------------------------------------------------------------------
extern "C" void kernel_launch(void* const* d_in, const int* in_sizes, int n_in,
                              void* d_out, int out_size)
{
    const float* x   = (const float*)d_in[0];
    const float* y   = (const float*)d_in[1];
    const float* w1  = (const float*)d_in[2];
    const float* b1  = (const float*)d_in[3];
    const float* w2  = (const float*)d_in[4];
    const float* b2  = (const float*)d_in[5];
    const float* wc1 = (const float*)d_in[6];
    const float* bc1 = (const float*)d_in[7];
    const float* wc2 = (const float*)d_in[8];
    const float* bc2 = (const float*)d_in[9];
    float* out = (float*)d_out;

    gate_kernel<<<B_ / 256, 256>>>(y, wc1, bc1, wc2, bc2);
    gemm1_kernel<<<dim3(NH_ / 128, B_ / 128), 256>>>(x, w1, b1);
    gemm2_kernel<<<dim3(C_ / 128, B_ / 128), 256>>>(w2, b2, out);
}

// round 3
// speedup vs baseline: 1.4276x; 1.4276x over previous
#include <cuda_runtime.h>
#include <cstdint>

// Problem constants
#define B_    8192
#define C_    4096
#define G_    8
#define HID_  1024
#define CTRL_ 64
#define NH_   (G_*HID_)

// GEMM tiling
#define BM 128
#define BN 128
#define BK 32
#define PADW 36                    // floats per smem row (32 + 4 pad)
#define ROWB (PADW*4)              // 144 bytes
#define STAGES 3
#define STAGE_BYTES ((BM+BN)*ROWB) // 36864
#define SMEM_BYTES (STAGES*STAGE_BYTES)  // 110592
#define GM 16                      // m-tiles per rasterization group

// Scratch (static device arrays: sanctioned workaround for alloc guard)
__device__ float g_x32[(size_t)B_ * C_];
__device__ float g_w1t[(size_t)NH_ * C_];   // [n=G*HID][k=C]
__device__ float g_w2t[(size_t)C_ * NH_];   // [n=C][k=NH]
__device__ float g_H  [(size_t)B_ * NH_];
__device__ float g_choose[B_ * G_];

// ---------------------------------------------------------------------------
// helpers
// ---------------------------------------------------------------------------
__device__ __forceinline__ unsigned f2tf32(float x) {
    unsigned u;
    asm("cvt.rna.tf32.f32 %0, %1;" : "=r"(u) : "f"(x));
    return u;
}
__device__ __forceinline__ float roundtf(float x) { return __uint_as_float(f2tf32(x)); }

__device__ __forceinline__ uint32_t smem_u32(const void* p) {
    uint32_t a;
    asm("{ .reg .u64 t; cvta.to.shared.u64 t, %1; cvt.u32.u64 %0, t; }" : "=r"(a) : "l"(p));
    return a;
}

__device__ __forceinline__ void cp_async16(uint32_t dst, const void* src) {
    asm volatile("cp.async.cg.shared.global [%0], [%1], 16;" :: "r"(dst), "l"(src) : "memory");
}

__device__ __forceinline__ void ldsm4(uint32_t r[4], uint32_t saddr) {
    asm volatile("ldmatrix.sync.aligned.m8n8.x4.shared.b16 {%0,%1,%2,%3}, [%4];"
        : "=r"(r[0]), "=r"(r[1]), "=r"(r[2]), "=r"(r[3]) : "r"(saddr));
}

__device__ __forceinline__ void mma_m16n8k8(float c[4], const uint32_t a[4],
                                            uint32_t b0, uint32_t b1) {
    asm volatile(
        "mma.sync.aligned.m16n8k8.row.col.f32.tf32.tf32.f32 "
        "{%0,%1,%2,%3}, {%4,%5,%6,%7}, {%8,%9}, {%0,%1,%2,%3};"
        : "+f"(c[0]), "+f"(c[1]), "+f"(c[2]), "+f"(c[3])
        : "r"(a[0]), "r"(a[1]), "r"(a[2]), "r"(a[3]), "r"(b0), "r"(b1));
}

// rasterization: GM m-tiles per group, n varies slowest within group
__device__ __forceinline__ void tile_map(int Ntiles, int& mt, int& nt) {
    const int bid = blockIdx.x;
    const int per_g = GM * Ntiles;
    const int grp = bid / per_g;
    const int rem = bid - grp * per_g;
    mt = grp * GM + (rem % GM);
    nt = rem / GM;
}

// ---------------------------------------------------------------------------
// cp.async tile issue: A tile [BM x BK], B tile [BN x BK], both K-contiguous
// ---------------------------------------------------------------------------
__device__ __forceinline__ void issue_tile(uint32_t sA, uint32_t sB,
                                           const float* Ag, const float* Bg,
                                           int K, int tid)
{
#pragma unroll
    for (int i = 0; i < 4; i++) {
        const int id = tid + 256 * i;
        const int row = id >> 3, c = id & 7;
        cp_async16(sA + row * ROWB + c * 16, Ag + (size_t)row * K + c * 4);
    }
#pragma unroll
    for (int i = 0; i < 4; i++) {
        const int id = tid + 256 * i;
        const int row = id >> 3, c = id & 7;
        cp_async16(sB + row * ROWB + c * 16, Bg + (size_t)row * K + c * 4);
    }
}

// ---------------------------------------------------------------------------
// mainloop: acc[4][4][4] = A[m0:m0+128, :K] * B[n0:n0+128, :K]^T
// A, B both row-major [rows][K] (K contiguous), pre-rounded to tf32 values.
// ---------------------------------------------------------------------------
__device__ __forceinline__ void mainloop(const float* __restrict__ A,
                                         const float* __restrict__ Bw,
                                         int K, int m0, int n0, char* smem,
                                         float (&acc)[4][4][4])
{
    const int tid  = threadIdx.x;
    const int lane = tid & 31;
    const int warp = tid >> 5;
    const int wm = (warp & 1) * 64;   // 2 warps in M
    const int wn = (warp >> 1) * 32;  // 4 warps in N
    const uint32_t sbase = smem_u32(smem);

#pragma unroll
    for (int i = 0; i < 4; i++)
#pragma unroll
        for (int j = 0; j < 4; j++)
#pragma unroll
            for (int k = 0; k < 4; k++) acc[i][j][k] = 0.f;

    const float* Ag = A  + (size_t)m0 * K;
    const float* Bg = Bw + (size_t)n0 * K;
    const int T = K / BK;

    // prologue: issue stages 0..STAGES-2
#pragma unroll
    for (int s = 0; s < STAGES - 1; s++) {
        issue_tile(sbase + s * STAGE_BYTES, sbase + s * STAGE_BYTES + BM * ROWB,
                   Ag + s * BK, Bg + s * BK, K, tid);
        asm volatile("cp.async.commit_group;" ::: "memory");
    }

    // per-lane ldmatrix address components
    const int rsel  = lane & 15;           // row within 16-row tile
    const int koffB = (lane >> 4) * 16;    // 0 or 16 bytes (k half)
    const uint32_t aOff = (uint32_t)((wm + rsel) * ROWB + koffB);
    const uint32_t bOff = (uint32_t)(BM * ROWB + (wn + rsel) * ROWB + koffB);

    for (int t = 0; t < T; t++) {
        asm volatile("cp.async.wait_group %0;" :: "n"(STAGES - 2) : "memory");
        __syncthreads();

        if (t + STAGES - 1 < T) {
            const int s2 = (t + STAGES - 1) % STAGES;
            issue_tile(sbase + s2 * STAGE_BYTES,
                       sbase + s2 * STAGE_BYTES + BM * ROWB,
                       Ag + (size_t)(t + STAGES - 1) * BK,
                       Bg + (size_t)(t + STAGES - 1) * BK, K, tid);
        }
        asm volatile("cp.async.commit_group;" ::: "memory");

        const uint32_t st = sbase + (uint32_t)((t % STAGES) * STAGE_BYTES);
#pragma unroll
        for (int k8 = 0; k8 < 4; k8++) {
            uint32_t a[4][4], bf[2][4];
#pragma unroll
            for (int im = 0; im < 4; im++)
                ldsm4(a[im], st + aOff + im * (16 * ROWB) + k8 * 32);
#pragma unroll
            for (int p = 0; p < 2; p++)
                ldsm4(bf[p], st + bOff + p * (16 * ROWB) + k8 * 32);
#pragma unroll
            for (int im = 0; im < 4; im++)
#pragma unroll
                for (int in = 0; in < 4; in++)
                    mma_m16n8k8(acc[im][in], a[im],
                                bf[in >> 1][in & 1], bf[in >> 1][2 + (in & 1)]);
        }
    }
    __syncthreads();   // smem safe for epilogue reuse
}

// ---------------------------------------------------------------------------
// GEMM1: H[m, n] = round_tf32( relu(x @ w1t[n,:]^T + b1[n]) * choose[m, n/1024] )
// ---------------------------------------------------------------------------
__global__ void __launch_bounds__(256, 2)
gemm1_k(const float* __restrict__ A, const float* __restrict__ Bw,
        const float* __restrict__ b1)
{
    extern __shared__ char smem[];
    int mt, nt;
    tile_map(NH_ / BN, mt, nt);
    const int m0 = mt * BM, n0 = nt * BN;
    const int g = n0 / HID_;

    float acc[4][4][4];
    mainloop(A, Bw, C_, m0, n0, smem, acc);

    const int tid = threadIdx.x, lane = tid & 31, warp = tid >> 5;
    const int wm = (warp & 1) * 64, wn = (warp >> 1) * 32;
    const int g8 = lane >> 2, tg = lane & 3;
    const float* b1g = b1 + (size_t)g * HID_ + (n0 % HID_);

#pragma unroll
    for (int im = 0; im < 4; im++) {
        const int r0 = m0 + wm + 16 * im + g8;
        const float ch0 = g_choose[r0 * G_ + g];
        const float ch1 = g_choose[(r0 + 8) * G_ + g];
#pragma unroll
        for (int in = 0; in < 4; in++) {
            const int cl = wn + 8 * in + 2 * tg;
            const float bb0 = __ldg(b1g + cl);
            const float bb1 = __ldg(b1g + cl + 1);
            float2 v0, v1;
            v0.x = roundtf(fmaxf(acc[im][in][0] + bb0, 0.f) * ch0);
            v0.y = roundtf(fmaxf(acc[im][in][1] + bb1, 0.f) * ch0);
            v1.x = roundtf(fmaxf(acc[im][in][2] + bb0, 0.f) * ch1);
            v1.y = roundtf(fmaxf(acc[im][in][3] + bb1, 0.f) * ch1);
            *reinterpret_cast<float2*>(&g_H[(size_t)r0 * NH_ + n0 + cl]) = v0;
            *reinterpret_cast<float2*>(&g_H[(size_t)(r0 + 8) * NH_ + n0 + cl]) = v1;
        }
    }
}

// ---------------------------------------------------------------------------
// GEMM2: out[m, c] = H @ w2t[c,:]^T + sum_g choose[m,g] * b2[g,c]
// ---------------------------------------------------------------------------
__global__ void __launch_bounds__(256, 2)
gemm2_k(const float* __restrict__ A, const float* __restrict__ Bw,
        const float* __restrict__ b2, float* __restrict__ out)
{
    extern __shared__ char smem[];
    int mt, nt;
    tile_map(C_ / BN, mt, nt);
    const int m0 = mt * BM, n0 = nt * BN;

    float acc[4][4][4];
    mainloop(A, Bw, NH_, m0, n0, smem, acc);

    // stage b2 tile [G][BN] in smem
    float* sB2 = (float*)smem;
    const int tid = threadIdx.x;
    for (int i = tid; i < G_ * BN; i += 256)
        sB2[i] = b2[(size_t)(i >> 7) * C_ + n0 + (i & 127)];
    __syncthreads();

    const int lane = tid & 31, warp = tid >> 5;
    const int wm = (warp & 1) * 64, wn = (warp >> 1) * 32;
    const int g8 = lane >> 2, tg = lane & 3;

#pragma unroll
    for (int im = 0; im < 4; im++) {
        const int r0 = m0 + wm + 16 * im + g8;
        float c0[G_], c1[G_];
        *reinterpret_cast<float4*>(&c0[0]) = *reinterpret_cast<const float4*>(&g_choose[r0 * G_]);
        *reinterpret_cast<float4*>(&c0[4]) = *reinterpret_cast<const float4*>(&g_choose[r0 * G_ + 4]);
        *reinterpret_cast<float4*>(&c1[0]) = *reinterpret_cast<const float4*>(&g_choose[(r0 + 8) * G_]);
        *reinterpret_cast<float4*>(&c1[4]) = *reinterpret_cast<const float4*>(&g_choose[(r0 + 8) * G_ + 4]);
#pragma unroll
        for (int in = 0; in < 4; in++) {
            const int cl = wn + 8 * in + 2 * tg;
            float b00 = 0.f, b01 = 0.f, b10 = 0.f, b11 = 0.f;
#pragma unroll
            for (int gg = 0; gg < G_; gg++) {
                const float w0 = sB2[gg * BN + cl];
                const float w1v = sB2[gg * BN + cl + 1];
                b00 += c0[gg] * w0;  b01 += c0[gg] * w1v;
                b10 += c1[gg] * w0;  b11 += c1[gg] * w1v;
            }
            float2 v0, v1;
            v0.x = acc[im][in][0] + b00;  v0.y = acc[im][in][1] + b01;
            v1.x = acc[im][in][2] + b10;  v1.y = acc[im][in][3] + b11;
            *reinterpret_cast<float2*>(&out[(size_t)r0 * C_ + n0 + cl]) = v0;
            *reinterpret_cast<float2*>(&out[(size_t)(r0 + 8) * C_ + n0 + cl]) = v1;
        }
    }
}

// ---------------------------------------------------------------------------
// Pre-pass: tf32(rna)-round copy, and transpose+round
// ---------------------------------------------------------------------------
__global__ void __launch_bounds__(256) round_copy(const float4* __restrict__ in,
                                                  float4* __restrict__ out, size_t n4)
{
    for (size_t i = (size_t)blockIdx.x * blockDim.x + threadIdx.x; i < n4;
         i += (size_t)gridDim.x * blockDim.x) {
        float4 v = in[i];
        v.x = roundtf(v.x); v.y = roundtf(v.y);
        v.z = roundtf(v.z); v.w = roundtf(v.w);
        out[i] = v;
    }
}

// in: [R, Cc] row-major -> out: [Cc, R] row-major, batched over blockIdx.z
__global__ void __launch_bounds__(256) transpose_round(const float* __restrict__ in,
                                                       float* __restrict__ out,
                                                       int R, int Cc)
{
    __shared__ float tile[32][33];
    const size_t boff = (size_t)blockIdx.z * R * Cc;
    in += boff; out += boff;
    const int x = blockIdx.x * 32 + threadIdx.x;
    const int y = blockIdx.y * 32 + threadIdx.y;
#pragma unroll
    for (int j = 0; j < 32; j += 8)
        tile[threadIdx.y + j][threadIdx.x] = roundtf(in[(size_t)(y + j) * Cc + x]);
    __syncthreads();
    const int x2 = blockIdx.y * 32 + threadIdx.x;
    const int y2 = blockIdx.x * 32 + threadIdx.y;
#pragma unroll
    for (int j = 0; j < 32; j += 8)
        out[(size_t)(y2 + j) * R + x2] = tile[threadIdx.x][threadIdx.y + j];
}

// ---------------------------------------------------------------------------
// Gate control: choose = softmax(relu(y@wc1+bc1)@wc2+bc2)
// ---------------------------------------------------------------------------
__global__ __launch_bounds__(256)
void gate_kernel(const float* __restrict__ y,
                 const float* __restrict__ wc1, const float* __restrict__ bc1,
                 const float* __restrict__ wc2, const float* __restrict__ bc2)
{
    __shared__ float swc1[CTRL_ * G_];
    __shared__ float swc2[G_ * G_];
    __shared__ float sbc1[G_];
    __shared__ float sbc2[G_];
    const int tid = threadIdx.x;
    for (int i = tid; i < CTRL_ * G_; i += 256) swc1[i] = wc1[i];
    if (tid < G_ * G_) swc2[tid] = wc2[tid];
    if (tid < G_) { sbc1[tid] = bc1[tid]; sbc2[tid] = bc2[tid]; }
    __syncthreads();

    const int b = blockIdx.x * 256 + tid;
    const float* yr = y + (size_t)b * CTRL_;

    float hid[G_];
#pragma unroll
    for (int j = 0; j < G_; j++) hid[j] = sbc1[j];
    for (int c = 0; c < CTRL_; c++) {
        const float yv = yr[c];
#pragma unroll
        for (int j = 0; j < G_; j++) hid[j] += yv * swc1[c * G_ + j];
    }
#pragma unroll
    for (int j = 0; j < G_; j++) hid[j] = fmaxf(hid[j], 0.f);

    float o[G_];
#pragma unroll
    for (int g = 0; g < G_; g++) o[g] = sbc2[g];
#pragma unroll
    for (int j = 0; j < G_; j++)
#pragma unroll
        for (int g = 0; g < G_; g++) o[g] += hid[j] * swc2[j * G_ + g];

    float mx = o[0];
#pragma unroll
    for (int g = 1; g < G_; g++) mx = fmaxf(mx, o[g]);
    float s = 0.f;
#pragma unroll
    for (int g = 0; g < G_; g++) { o[g] = __expf(o[g] - mx); s += o[g]; }
    const float inv = 1.f / s;
#pragma unroll
    for (int g = 0; g < G_; g++) g_choose[b * G_ + g] = o[g] * inv;
}

// ---------------------------------------------------------------------------
extern "C" void kernel_launch(void* const* d_in, const int* in_sizes, int n_in,
                              void* d_out, int out_size)
{
    const float* x   = (const float*)d_in[0];
    const float* y   = (const float*)d_in[1];
    const float* w1  = (const float*)d_in[2];
    const float* b1  = (const float*)d_in[3];
    const float* w2  = (const float*)d_in[4];
    const float* b2  = (const float*)d_in[5];
    const float* wc1 = (const float*)d_in[6];
    const float* bc1 = (const float*)d_in[7];
    const float* wc2 = (const float*)d_in[8];
    const float* bc2 = (const float*)d_in[9];
    float* out = (float*)d_out;

    cudaFuncSetAttribute(gemm1_k, cudaFuncAttributeMaxDynamicSharedMemorySize, SMEM_BYTES);
    cudaFuncSetAttribute(gemm2_k, cudaFuncAttributeMaxDynamicSharedMemorySize, SMEM_BYTES);

    float* dx32;  cudaGetSymbolAddress((void**)&dx32, g_x32);
    float* dw1t;  cudaGetSymbolAddress((void**)&dw1t, g_w1t);
    float* dw2t;  cudaGetSymbolAddress((void**)&dw2t, g_w2t);
    float* dH;    cudaGetSymbolAddress((void**)&dH,   g_H);

    // pre-pass: rna-round x; transpose+round w1 ([C,HID]/gate -> [HID,C]) and
    // w2 ([NH,C] -> [C,NH])
    round_copy<<<1024, 256>>>((const float4*)x, (float4*)dx32, (size_t)B_ * C_ / 4);
    transpose_round<<<dim3(HID_ / 32, C_ / 32, G_), dim3(32, 8)>>>(w1, dw1t, C_, HID_);
    transpose_round<<<dim3(C_ / 32, NH_ / 32, 1), dim3(32, 8)>>>(w2, dw2t, NH_, C_);
    gate_kernel<<<B_ / 256, 256>>>(y, wc1, bc1, wc2, bc2);

    gemm1_k<<<(B_ / BM) * (NH_ / BN), 256, SMEM_BYTES>>>(dx32, dw1t, b1);
    gemm2_k<<<(B_ / BM) * (C_ / BN), 256, SMEM_BYTES>>>(dH, dw2t, b2, out);
}

// round 5
// speedup vs baseline: 2.7698x; 1.9402x over previous
#include <cuda_runtime.h>
#include <cuda_fp16.h>
#include <cstdint>

// Problem constants
#define B_    8192
#define C_    4096
#define G_    8
#define HID_  1024
#define CTRL_ 64
#define NH_   (G_*HID_)

// GEMM tiling (fp16 elements)
#define BM 128
#define BN 128
#define BK 64                       // halves per K-chunk (128 bytes)
#define ROWB 144                    // 128B data + 16B pad per smem row
#define STAGES 3
#define STAGE_BYTES ((BM+BN)*ROWB)  // 36864
#define SMEM_BYTES (STAGES*STAGE_BYTES)  // 110592
#define GM 16                       // m-tiles per rasterization group

// Scratch (static device arrays: sanctioned workaround for alloc guard)
__device__ __half g_xh [(size_t)B_ * C_];
__device__ __half g_w1t[(size_t)NH_ * C_];   // [n=G*HID][k=C]
__device__ __half g_w2t[(size_t)C_ * NH_];   // [n=C][k=NH]
__device__ __half g_H  [(size_t)B_ * NH_];
__device__ float  g_choose[B_ * G_];

// ---------------------------------------------------------------------------
// helpers
// ---------------------------------------------------------------------------
__device__ __forceinline__ unsigned h2_bits(__half2 h) {
    return *reinterpret_cast<unsigned*>(&h);
}

__device__ __forceinline__ uint32_t smem_u32(const void* p) {
    uint32_t a;
    asm("{ .reg .u64 t; cvta.to.shared.u64 t, %1; cvt.u32.u64 %0, t; }" : "=r"(a) : "l"(p));
    return a;
}

__device__ __forceinline__ void cp_async16(uint32_t dst, const void* src) {
    asm volatile("cp.async.cg.shared.global [%0], [%1], 16;" :: "r"(dst), "l"(src) : "memory");
}

__device__ __forceinline__ void ldsm4(uint32_t r[4], uint32_t saddr) {
    asm volatile("ldmatrix.sync.aligned.m8n8.x4.shared.b16 {%0,%1,%2,%3}, [%4];"
        : "=r"(r[0]), "=r"(r[1]), "=r"(r[2]), "=r"(r[3]) : "r"(saddr));
}

__device__ __forceinline__ void mma_f16(float c[4], const uint32_t a[4],
                                        uint32_t b0, uint32_t b1) {
    asm volatile(
        "mma.sync.aligned.m16n8k16.row.col.f32.f16.f16.f32 "
        "{%0,%1,%2,%3}, {%4,%5,%6,%7}, {%8,%9}, {%0,%1,%2,%3};"
        : "+f"(c[0]), "+f"(c[1]), "+f"(c[2]), "+f"(c[3])
        : "r"(a[0]), "r"(a[1]), "r"(a[2]), "r"(a[3]), "r"(b0), "r"(b1));
}

// rasterization: GM m-tiles per group, n varies slowest within group
__device__ __forceinline__ void tile_map(int Ntiles, int& mt, int& nt) {
    const int bid = blockIdx.x;
    const int per_g = GM * Ntiles;
    const int grp = bid / per_g;
    const int rem = bid - grp * per_g;
    mt = grp * GM + (rem % GM);
    nt = rem / GM;
}

// ---------------------------------------------------------------------------
// cp.async tile issue: A tile [BM x BK], B tile [BN x BK] halves, K-contiguous
// ---------------------------------------------------------------------------
__device__ __forceinline__ void issue_tile(uint32_t sA, uint32_t sB,
                                           const __half* Ag, const __half* Bg,
                                           int K, int tid)
{
#pragma unroll
    for (int i = 0; i < 4; i++) {
        const int id = tid + 256 * i;
        const int row = id >> 3, c = id & 7;
        cp_async16(sA + row * ROWB + c * 16, Ag + (size_t)row * K + c * 8);
    }
#pragma unroll
    for (int i = 0; i < 4; i++) {
        const int id = tid + 256 * i;
        const int row = id >> 3, c = id & 7;
        cp_async16(sB + row * ROWB + c * 16, Bg + (size_t)row * K + c * 8);
    }
}

// ---------------------------------------------------------------------------
// mainloop: acc[4][4][4] = A[m0:m0+128, :K] * B[n0:n0+128, :K]^T   (fp16 in)
// ---------------------------------------------------------------------------
__device__ __forceinline__ void mainloop(const __half* __restrict__ A,
                                         const __half* __restrict__ Bw,
                                         int K, int m0, int n0, char* smem,
                                         float (&acc)[4][4][4])
{
    const int tid  = threadIdx.x;
    const int lane = tid & 31;
    const int warp = tid >> 5;
    const int wm = (warp & 1) * 64;   // 2 warps in M
    const int wn = (warp >> 1) * 32;  // 4 warps in N
    const uint32_t sbase = smem_u32(smem);

#pragma unroll
    for (int i = 0; i < 4; i++)
#pragma unroll
        for (int j = 0; j < 4; j++)
#pragma unroll
            for (int k = 0; k < 4; k++) acc[i][j][k] = 0.f;

    const __half* Ag = A  + (size_t)m0 * K;
    const __half* Bg = Bw + (size_t)n0 * K;
    const int T = K / BK;

#pragma unroll
    for (int s = 0; s < STAGES - 1; s++) {
        issue_tile(sbase + s * STAGE_BYTES, sbase + s * STAGE_BYTES + BM * ROWB,
                   Ag + (size_t)s * BK, Bg + (size_t)s * BK, K, tid);
        asm volatile("cp.async.commit_group;" ::: "memory");
    }

    // per-lane ldmatrix address components (b16 x4: 16 rows, two 16B k-halves)
    const int rsel  = lane & 15;
    const int koffB = (lane >> 4) * 16;
    const uint32_t aOff = (uint32_t)((wm + rsel) * ROWB + koffB);
    const uint32_t bOff = (uint32_t)(BM * ROWB + (wn + rsel) * ROWB + koffB);

    for (int t = 0; t < T; t++) {
        asm volatile("cp.async.wait_group %0;" :: "n"(STAGES - 2) : "memory");
        __syncthreads();

        if (t + STAGES - 1 < T) {
            const int s2 = (t + STAGES - 1) % STAGES;
            issue_tile(sbase + s2 * STAGE_BYTES,
                       sbase + s2 * STAGE_BYTES + BM * ROWB,
                       Ag + (size_t)(t + STAGES - 1) * BK,
                       Bg + (size_t)(t + STAGES - 1) * BK, K, tid);
        }
        asm volatile("cp.async.commit_group;" ::: "memory");

        const uint32_t st = sbase + (uint32_t)((t % STAGES) * STAGE_BYTES);
#pragma unroll
        for (int k16 = 0; k16 < 4; k16++) {          // 4 x k16 per BK=64
            uint32_t a[4][4], bf[2][4];
#pragma unroll
            for (int im = 0; im < 4; im++)
                ldsm4(a[im], st + aOff + im * (16 * ROWB) + k16 * 32);
#pragma unroll
            for (int p = 0; p < 2; p++)
                ldsm4(bf[p], st + bOff + p * (16 * ROWB) + k16 * 32);
#pragma unroll
            for (int im = 0; im < 4; im++)
#pragma unroll
                for (int in = 0; in < 4; in++)
                    mma_f16(acc[im][in], a[im],
                            bf[in >> 1][in & 1], bf[in >> 1][2 + (in & 1)]);
        }
    }
    __syncthreads();   // smem safe for epilogue reuse
}

// ---------------------------------------------------------------------------
// GEMM1: H[m, n] = fp16( relu(x @ w1t[n,:]^T + b1[n]) * choose[m, n/1024] )
// ---------------------------------------------------------------------------
__global__ void __launch_bounds__(256, 2)
gemm1_k(const __half* __restrict__ A, const __half* __restrict__ Bw,
        const float* __restrict__ b1)
{
    extern __shared__ char smem[];
    int mt, nt;
    tile_map(NH_ / BN, mt, nt);
    const int m0 = mt * BM, n0 = nt * BN;
    const int g = n0 / HID_;

    float acc[4][4][4];
    mainloop(A, Bw, C_, m0, n0, smem, acc);

    const int tid = threadIdx.x, lane = tid & 31, warp = tid >> 5;
    const int wm = (warp & 1) * 64, wn = (warp >> 1) * 32;
    const int g8 = lane >> 2, tg = lane & 3;
    const float* b1g = b1 + (size_t)g * HID_ + (n0 % HID_);

#pragma unroll
    for (int im = 0; im < 4; im++) {
        const int r0 = m0 + wm + 16 * im + g8;
        const float ch0 = g_choose[r0 * G_ + g];
        const float ch1 = g_choose[(r0 + 8) * G_ + g];
#pragma unroll
        for (int in = 0; in < 4; in++) {
            const int cl = wn + 8 * in + 2 * tg;
            const float bb0 = __ldg(b1g + cl);
            const float bb1 = __ldg(b1g + cl + 1);
            __half2 v0 = __floats2half2_rn(fmaxf(acc[im][in][0] + bb0, 0.f) * ch0,
                                           fmaxf(acc[im][in][1] + bb1, 0.f) * ch0);
            __half2 v1 = __floats2half2_rn(fmaxf(acc[im][in][2] + bb0, 0.f) * ch1,
                                           fmaxf(acc[im][in][3] + bb1, 0.f) * ch1);
            *reinterpret_cast<__half2*>(&g_H[(size_t)r0 * NH_ + n0 + cl]) = v0;
            *reinterpret_cast<__half2*>(&g_H[(size_t)(r0 + 8) * NH_ + n0 + cl]) = v1;
        }
    }
}

// ---------------------------------------------------------------------------
// GEMM2: out[m, c] = H @ w2t[c,:]^T + sum_g choose[m,g] * b2[g,c]
// ---------------------------------------------------------------------------
__global__ void __launch_bounds__(256, 2)
gemm2_k(const __half* __restrict__ A, const __half* __restrict__ Bw,
        const float* __restrict__ b2, float* __restrict__ out)
{
    extern __shared__ char smem[];
    int mt, nt;
    tile_map(C_ / BN, mt, nt);
    const int m0 = mt * BM, n0 = nt * BN;

    float acc[4][4][4];
    mainloop(A, Bw, NH_, m0, n0, smem, acc);

    // stage b2 tile [G][BN] in smem
    float* sB2 = (float*)smem;
    const int tid = threadIdx.x;
    for (int i = tid; i < G_ * BN; i += 256)
        sB2[i] = b2[(size_t)(i >> 7) * C_ + n0 + (i & 127)];
    __syncthreads();

    const int lane = tid & 31, warp = tid >> 5;
    const int wm = (warp & 1) * 64, wn = (warp >> 1) * 32;
    const int g8 = lane >> 2, tg = lane & 3;

#pragma unroll
    for (int im = 0; im < 4; im++) {
        const int r0 = m0 + wm + 16 * im + g8;
        float c0[G_], c1[G_];
        *reinterpret_cast<float4*>(&c0[0]) = *reinterpret_cast<const float4*>(&g_choose[r0 * G_]);
        *reinterpret_cast<float4*>(&c0[4]) = *reinterpret_cast<const float4*>(&g_choose[r0 * G_ + 4]);
        *reinterpret_cast<float4*>(&c1[0]) = *reinterpret_cast<const float4*>(&g_choose[(r0 + 8) * G_]);
        *reinterpret_cast<float4*>(&c1[4]) = *reinterpret_cast<const float4*>(&g_choose[(r0 + 8) * G_ + 4]);
#pragma unroll
        for (int in = 0; in < 4; in++) {
            const int cl = wn + 8 * in + 2 * tg;
            float b00 = 0.f, b01 = 0.f, b10 = 0.f, b11 = 0.f;
#pragma unroll
            for (int gg = 0; gg < G_; gg++) {
                const float w0  = sB2[gg * BN + cl];
                const float w1v = sB2[gg * BN + cl + 1];
                b00 += c0[gg] * w0;  b01 += c0[gg] * w1v;
                b10 += c1[gg] * w0;  b11 += c1[gg] * w1v;
            }
            float2 v0, v1;
            v0.x = acc[im][in][0] + b00;  v0.y = acc[im][in][1] + b01;
            v1.x = acc[im][in][2] + b10;  v1.y = acc[im][in][3] + b11;
            *reinterpret_cast<float2*>(&out[(size_t)r0 * C_ + n0 + cl]) = v0;
            *reinterpret_cast<float2*>(&out[(size_t)(r0 + 8) * C_ + n0 + cl]) = v1;
        }
    }
}

// ---------------------------------------------------------------------------
// Pre-pass: fp32 -> fp16 copy, and fp32 -> fp16 transpose
// ---------------------------------------------------------------------------
__global__ void __launch_bounds__(256) f2h_copy(const float4* __restrict__ in,
                                                uint4* __restrict__ out, size_t n8)
{
    for (size_t i = (size_t)blockIdx.x * blockDim.x + threadIdx.x; i < n8;
         i += (size_t)gridDim.x * blockDim.x) {
        float4 v0 = in[2 * i];
        float4 v1 = in[2 * i + 1];
        uint4 o;
        o.x = h2_bits(__floats2half2_rn(v0.x, v0.y));
        o.y = h2_bits(__floats2half2_rn(v0.z, v0.w));
        o.z = h2_bits(__floats2half2_rn(v1.x, v1.y));
        o.w = h2_bits(__floats2half2_rn(v1.z, v1.w));
        out[i] = o;
    }
}

// in: [R, Cc] fp32 row-major -> out: [Cc, R] fp16 row-major, batched over z
__global__ void __launch_bounds__(256) transpose_h(const float* __restrict__ in,
                                                   __half* __restrict__ out,
                                                   int R, int Cc)
{
    __shared__ float tile[32][33];
    const size_t z = blockIdx.z;
    in  += z * (size_t)R * Cc;
    out += z * (size_t)R * Cc;
    const int x = blockIdx.x * 32 + threadIdx.x;
    const int y = blockIdx.y * 32 + threadIdx.y;
#pragma unroll
    for (int j = 0; j < 32; j += 8)
        tile[threadIdx.y + j][threadIdx.x] = in[(size_t)(y + j) * Cc + x];
    __syncthreads();
    const int x2 = blockIdx.y * 32 + threadIdx.x;
    const int y2 = blockIdx.x * 32 + threadIdx.y;
#pragma unroll
    for (int j = 0; j < 32; j += 8)
        out[(size_t)(y2 + j) * R + x2] = __float2half_rn(tile[threadIdx.x][threadIdx.y + j]);
}

// ---------------------------------------------------------------------------
// Gate control: choose = softmax(relu(y@wc1+bc1)@wc2+bc2)
// ---------------------------------------------------------------------------
__global__ __launch_bounds__(256)
void gate_kernel(const float* __restrict__ y,
                 const float* __restrict__ wc1, const float* __restrict__ bc1,
                 const float* __restrict__ wc2, const float* __restrict__ bc2)
{
    __shared__ float swc1[CTRL_ * G_];
    __shared__ float swc2[G_ * G_];
    __shared__ float sbc1[G_];
    __shared__ float sbc2[G_];
    const int tid = threadIdx.x;
    for (int i = tid; i < CTRL_ * G_; i += 256) swc1[i] = wc1[i];
    if (tid < G_ * G_) swc2[tid] = wc2[tid];
    if (tid < G_) { sbc1[tid] = bc1[tid]; sbc2[tid] = bc2[tid]; }
    __syncthreads();

    const int b = blockIdx.x * 256 + tid;
    const float* yr = y + (size_t)b * CTRL_;

    float hid[G_];
#pragma unroll
    for (int j = 0; j < G_; j++) hid[j] = sbc1[j];
    for (int c = 0; c < CTRL_; c++) {
        const float yv = yr[c];
#pragma unroll
        for (int j = 0; j < G_; j++) hid[j] += yv * swc1[c * G_ + j];
    }
#pragma unroll
    for (int j = 0; j < G_; j++) hid[j] = fmaxf(hid[j], 0.f);

    float o[G_];
#pragma unroll
    for (int g = 0; g < G_; g++) o[g] = sbc2[g];
#pragma unroll
    for (int j = 0; j < G_; j++)
#pragma unroll
        for (int g = 0; g < G_; g++) o[g] += hid[j] * swc2[j * G_ + g];

    float mx = o[0];
#pragma unroll
    for (int g = 1; g < G_; g++) mx = fmaxf(mx, o[g]);
    float s = 0.f;
#pragma unroll
    for (int g = 0; g < G_; g++) { o[g] = __expf(o[g] - mx); s += o[g]; }
    const float inv = 1.f / s;
#pragma unroll
    for (int g = 0; g < G_; g++) g_choose[b * G_ + g] = o[g] * inv;
}

// ---------------------------------------------------------------------------
extern "C" void kernel_launch(void* const* d_in, const int* in_sizes, int n_in,
                              void* d_out, int out_size)
{
    const float* x   = (const float*)d_in[0];
    const float* y   = (const float*)d_in[1];
    const float* w1  = (const float*)d_in[2];
    const float* b1  = (const float*)d_in[3];
    const float* w2  = (const float*)d_in[4];
    const float* b2  = (const float*)d_in[5];
    const float* wc1 = (const float*)d_in[6];
    const float* bc1 = (const float*)d_in[7];
    const float* wc2 = (const float*)d_in[8];
    const float* bc2 = (const float*)d_in[9];
    float* out = (float*)d_out;

    cudaFuncSetAttribute(gemm1_k, cudaFuncAttributeMaxDynamicSharedMemorySize, SMEM_BYTES);
    cudaFuncSetAttribute(gemm2_k, cudaFuncAttributeMaxDynamicSharedMemorySize, SMEM_BYTES);

    __half* dxh;  cudaGetSymbolAddress((void**)&dxh,  g_xh);
    __half* dw1t; cudaGetSymbolAddress((void**)&dw1t, g_w1t);
    __half* dw2t; cudaGetSymbolAddress((void**)&dw2t, g_w2t);
    __half* dH;   cudaGetSymbolAddress((void**)&dH,   g_H);

    // pre-pass: x -> fp16; transpose w1 ([C,HID]/gate -> [HID,C]) and
    // w2 ([NH,C] -> [C,NH]) to fp16
    f2h_copy<<<1024, 256>>>((const float4*)x, (uint4*)dxh, (size_t)B_ * C_ / 8);
    transpose_h<<<dim3(HID_ / 32, C_ / 32, G_), dim3(32, 8)>>>(w1, dw1t, C_, HID_);
    transpose_h<<<dim3(C_ / 32, NH_ / 32, 1), dim3(32, 8)>>>(w2, dw2t, NH_, C_);
    gate_kernel<<<B_ / 256, 256>>>(y, wc1, bc1, wc2, bc2);

    gemm1_k<<<(B_ / BM) * (NH_ / BN), 256, SMEM_BYTES>>>(dxh, dw1t, b1);
    gemm2_k<<<(B_ / BM) * (C_ / BN), 256, SMEM_BYTES>>>(dH, dw2t, b2, out);
}